// round 13
// baseline (speedup 1.0000x reference)
#include <cuda_runtime.h>
#include <cuda_bf16.h>
#include <math.h>
#include <stdint.h>

constexpr int B   = 256;
constexpr int S   = 512;
constexpr int T   = B * S;       // 131072 tokens
constexpr int MEM = 32;
constexpr int DK  = 128;
constexpr int DV  = 128;
constexpr int DS  = 256;

// ---------------- scratch ----------------
__device__ float g_w    [(size_t)T * MEM];
__device__ float g_erase[(size_t)T * DV];
__device__ float g_add  [(size_t)T * DV];
__device__ float g_pa   [(size_t)2 * T];
__device__ float g_pd   [(size_t)T];

__device__ __nv_bfloat16 g_qe_h[(size_t)T * 128], g_qe_l[(size_t)T * 128];
__device__ __nv_bfloat16 g_qa_h[(size_t)T * 128], g_qa_l[(size_t)T * 128];
__device__ __nv_bfloat16 g_rd_h[(size_t)T * 128], g_rd_l[(size_t)T * 128];
__device__ __nv_bfloat16 g_sm_h[(size_t)T * 256], g_sm_l[(size_t)T * 256];

__device__ __nv_bfloat16 g_We_h[128*128], g_We_l[128*128];
__device__ __nv_bfloat16 g_Wa_h[128*128], g_Wa_l[128*128];
__device__ __nv_bfloat16 g_Wd_h[128*128], g_Wd_l[128*128];
__device__ __nv_bfloat16 g_Ws_h[256*256], g_Ws_l[256*256];
__device__ __nv_bfloat16 g_Wb_h[256*256], g_Wb_l[256*256];

__device__ __forceinline__ float actf(float x, int a) {
    if (a == 1) return 1.f / (1.f + expf(-x));
    if (a == 2) return tanhf(x);
    return x;
}
__device__ __forceinline__ uint32_t pack_hi(float x, float y) {
    __nv_bfloat16 hx = __float2bfloat16(x);
    __nv_bfloat16 hy = __float2bfloat16(y);
    return ((uint32_t)__bfloat16_as_ushort(hy) << 16) | __bfloat16_as_ushort(hx);
}
__device__ __forceinline__ uint32_t pack_lo(float x, float y) {
    __nv_bfloat16 hx = __float2bfloat16(x);
    __nv_bfloat16 hy = __float2bfloat16(y);
    __nv_bfloat16 lx = __float2bfloat16(x - __bfloat162float(hx));
    __nv_bfloat16 ly = __float2bfloat16(y - __bfloat162float(hy));
    return ((uint32_t)__bfloat16_as_ushort(ly) << 16) | __bfloat16_as_ushort(lx);
}

// ---------------- prep: all 5 weights, one launch ----------------
__global__ __launch_bounds__(256) void prep_weight_all(
    const float* __restrict__ W0, const float* __restrict__ W1,
    const float* __restrict__ W2, const float* __restrict__ W3,
    const float* __restrict__ W4)
{
    int bid = blockIdx.x;
    const float* W; __nv_bfloat16 *th, *tl; int K, N, base;
    if (bid < 64)       { W = W0; th = g_We_h; tl = g_We_l; K = 128; N = 128; base = 0; }
    else if (bid < 128) { W = W1; th = g_Wa_h; tl = g_Wa_l; K = 128; N = 128; base = 64; }
    else if (bid < 192) { W = W2; th = g_Wd_h; tl = g_Wd_l; K = 128; N = 128; base = 128; }
    else if (bid < 448) { W = W3; th = g_Ws_h; tl = g_Ws_l; K = 256; N = 256; base = 192; }
    else                { W = W4; th = g_Wb_h; tl = g_Wb_l; K = 256; N = 256; base = 448; }
    int e = (bid - base) * 256 + threadIdx.x;
    int k = e / N, n = e - k * N;
    float v = W[e];
    __nv_bfloat16 h = __float2bfloat16(v);
    th[(size_t)n * K + k] = h;
    tl[(size_t)n * K + k] = __float2bfloat16(v - __bfloat162float(h));
}

// ---------------- prep: qa gather + fp32 -> bf16 hi/lo ----------------
__global__ __launch_bounds__(256) void prep_gather_qa(
    const int* __restrict__ qa_data, const float* __restrict__ qa_table)
{
    int t    = blockIdx.x * 8 + (threadIdx.x >> 5);
    int lane = threadIdx.x & 31;
    int row = qa_data[t];
    float4 v = *(const float4*)(qa_table + (size_t)row * 128 + lane * 4);
    uint2 h, l;
    h.x = pack_hi(v.x, v.y); h.y = pack_hi(v.z, v.w);
    l.x = pack_lo(v.x, v.y); l.y = pack_lo(v.z, v.w);
    *(uint2*)(g_qa_h + (size_t)t * 128 + lane * 4) = h;
    *(uint2*)(g_qa_l + (size_t)t * 128 + lane * 4) = l;
}

// ---------------- attention softmax + qe bf16 conversion ----------------
__global__ __launch_bounds__(256) void attn_kernel(
    const int* __restrict__ q_data,
    const float* __restrict__ q_table,
    const float* __restrict__ key_memory,
    float* __restrict__ w_out)
{
    __shared__ float ksm[32 * 129];
    int tid = threadIdx.x;
    for (int i = tid; i < 32 * 128; i += 256) {
        int m = i >> 7, k = i & 127;
        ksm[m * 129 + k] = key_memory[i];
    }
    __syncthreads();

    int warp = tid >> 5, lane = tid & 31;
    int t = blockIdx.x * 8 + warp;
    int row = q_data[t];

    float4 v = *(const float4*)(q_table + (size_t)row * 128 + lane * 4);
    uint2 hh, ll;
    hh.x = pack_hi(v.x, v.y); hh.y = pack_hi(v.z, v.w);
    ll.x = pack_lo(v.x, v.y); ll.y = pack_lo(v.z, v.w);
    *(uint2*)(g_qe_h + (size_t)t * 128 + lane * 4) = hh;
    *(uint2*)(g_qe_l + (size_t)t * 128 + lane * 4) = ll;

    float lg = 0.f;
    #pragma unroll
    for (int k = 0; k < 128; ++k) {
        float comp = ((k & 3) == 0) ? v.x : ((k & 3) == 1) ? v.y : ((k & 3) == 2) ? v.z : v.w;
        float qv = __shfl_sync(0xffffffffu, comp, k >> 2);
        lg = fmaf(qv, ksm[lane * 129 + k], lg);
    }
    float mx = lg;
    #pragma unroll
    for (int off = 16; off > 0; off >>= 1)
        mx = fmaxf(mx, __shfl_xor_sync(0xffffffffu, mx, off));
    float e = expf(lg - mx);
    float sum = e;
    #pragma unroll
    for (int off = 16; off > 0; off >>= 1)
        sum += __shfl_xor_sync(0xffffffffu, sum, off);
    w_out[(size_t)t * 32 + lane] = e / sum;
}

// ---------------- bf16x3 GEMM: 4 warps x (64x64), B-resident, 3-stage A ring ----------------
struct GDesc {
    const __nv_bfloat16 *a0h, *a0l; int p0, o0;
    const __nv_bfloat16 *a1h, *a1l; int p1, o1;
    const __nv_bfloat16 *wh, *wl;   int ldk, wcol;
    const float* bias;
    int act;
    int omode;      // 0 fp32 store, 1 bf16 hi/lo store, 2 dot-reduce
    float* outf; int ldo, ocol;
    __nv_bfloat16 *oh, *ol; int ldob, ocolb;
    const float* w2;
    float* pout;
};

__device__ __forceinline__ void mma16816(float* c, const uint32_t* a, const uint32_t* b) {
    asm volatile(
        "mma.sync.aligned.m16n8k16.row.col.f32.bf16.bf16.f32 "
        "{%0,%1,%2,%3}, {%4,%5,%6,%7}, {%8,%9}, {%0,%1,%2,%3};"
        : "+f"(c[0]), "+f"(c[1]), "+f"(c[2]), "+f"(c[3])
        : "r"(a[0]), "r"(a[1]), "r"(a[2]), "r"(a[3]), "r"(b[0]), "r"(b[1]));
}
#define LDSM4(r, addr) \
    asm volatile("ldmatrix.sync.aligned.m8n8.x4.shared.b16 {%0,%1,%2,%3}, [%4];" \
        : "=r"((r)[0]), "=r"((r)[1]), "=r"((r)[2]), "=r"((r)[3]) : "r"(addr))

__device__ __forceinline__ void cpa16(uint32_t dst, const void* src) {
    asm volatile("cp.async.cg.shared.global [%0], [%1], 16;" :: "r"(dst), "l"(src));
}

constexpr int APL  = 8192;
constexpr int AST  = 2 * APL;
constexpr int BPL  = 32768;
constexpr int AOFF = 2 * BPL;
constexpr int GSM  = AOFF + 3 * AST; // 114688 -> 2 CTAs/SM

__device__ __forceinline__ void prefetch_A(const GDesc& G, int tok0, int c,
                                           uint32_t stage_base, int tid)
{
    int kbase = c << 5;
    const __nv_bfloat16 *Ah, *Al; int Ap, Ao;
    if (kbase < 128) { Ah = G.a0h; Al = G.a0l; Ap = G.p0; Ao = G.o0 + kbase; }
    else             { Ah = G.a1h; Al = G.a1l; Ap = G.p1; Ao = G.o1 + kbase - 128; }
    #pragma unroll
    for (int j = 0; j < 4; ++j) {
        int e = tid + j * 128;
        int r = e >> 2, q = e & 3;
        int qs = q ^ ((r >> 1) & 3);
        size_t src = (size_t)(tok0 + r) * Ap + Ao + q * 8;
        uint32_t dst = stage_base + (uint32_t)(r * 64 + qs * 16);
        cpa16(dst,       Ah + src);
        cpa16(dst + APL, Al + src);
    }
}

__device__ __forceinline__ void load_B(const GDesc& G, int khalf, uint32_t sbase, int tid)
{
    #pragma unroll
    for (int j = 0; j < 16; ++j) {
        int e = tid + j * 128;
        int n = e >> 4, q = e & 15;
        int qs = q ^ (n & 7);
        size_t src = (size_t)(G.wcol + n) * G.ldk + khalf + q * 8;
        uint32_t dst = sbase + (uint32_t)(n * 256 + qs * 16);
        cpa16(dst,       G.wh + src);
        cpa16(dst + BPL, G.wl + src);
    }
}

__global__ __launch_bounds__(128, 2) void mma_gemm(int Ktot, GDesc G0, GDesc G1, GDesc G2)
{
    extern __shared__ __align__(16) uint32_t smw[];
    uint32_t sbase = (uint32_t)__cvta_generic_to_shared(smw);

    const GDesc G = (blockIdx.y == 0) ? G0 : ((blockIdx.y == 1) ? G1 : G2);

    int tid  = threadIdx.x;
    int wid  = tid >> 5, lane = tid & 31;
    int g    = lane >> 2, tq = lane & 3;
    int tok0 = blockIdx.x * 128;

    int wm = (wid & 1) * 64;     // warp M offset (64 rows)
    int wn = (wid >> 1) * 64;    // warp N offset (64 cols)

    int lane_r = lane & 15;
    int a_qb   = lane >> 4;
    int jb     = lane >> 3;
    uint32_t a_row[4]; int a_sw[4];
    #pragma unroll
    for (int mt = 0; mt < 4; ++mt) {
        int r = wm + mt * 16 + lane_r;
        a_row[mt] = (uint32_t)(r * 64);
        a_sw[mt]  = (r >> 1) & 3;
    }
    uint32_t b_row[4]; int b_sw[4];
    #pragma unroll
    for (int ntp = 0; ntp < 4; ++ntp) {
        int n = wn + ntp * 16 + ((jb >> 1) * 8) + (lane & 7);
        b_row[ntp] = (uint32_t)(n * 256);
        b_sw[ntp]  = n & 7;
    }
    int b_qb = jb & 1;

    float acc[4][8][4];
    #pragma unroll
    for (int i = 0; i < 4; ++i)
        #pragma unroll
        for (int j = 0; j < 8; ++j)
            #pragma unroll
            for (int u = 0; u < 4; ++u) acc[i][j][u] = 0.f;

    int nch = Ktot >> 5;

    load_B(G, 0, sbase, tid);
    prefetch_A(G, tok0, 0, sbase + AOFF, tid);
    asm volatile("cp.async.commit_group;");
    if (nch > 1) prefetch_A(G, tok0, 1, sbase + AOFF + AST, tid);
    asm volatile("cp.async.commit_group;");

    for (int c = 0; c < nch; ++c) {
        asm volatile("cp.async.wait_group 1;");
        __syncthreads();
        if (c == 4) {                         // only when nch == 8: B swap
            load_B(G, 128, sbase, tid);
            if (c + 2 < nch) {
                int s = (c + 2) % 3;
                prefetch_A(G, tok0, c + 2, sbase + AOFF + (uint32_t)s * AST, tid);
            }
            asm volatile("cp.async.commit_group;");
            asm volatile("cp.async.wait_group 0;");
            __syncthreads();
        } else {
            if (c + 2 < nch) {
                int s = (c + 2) % 3;
                prefetch_A(G, tok0, c + 2, sbase + AOFF + (uint32_t)s * AST, tid);
            }
            asm volatile("cp.async.commit_group;");
        }

        uint32_t Ab = sbase + AOFF + (uint32_t)(c % 3) * AST;
        int bq_c = (c & 3) * 4 + b_qb;

        #pragma unroll
        for (int h = 0; h < 2; ++h) {
            uint32_t ah[4][4], al[4][4], bh[4][4], bl[4][4];
            int aq = h * 2 + a_qb;
            int bq = bq_c + h * 2;
            // load ah, bh, bl first; al deferred (hidden under pass2)
            #pragma unroll
            for (int mt = 0; mt < 4; ++mt)
                LDSM4(ah[mt], Ab + a_row[mt] + (uint32_t)((aq ^ a_sw[mt]) << 4));
            #pragma unroll
            for (int ntp = 0; ntp < 4; ++ntp) {
                uint32_t addr = sbase + b_row[ntp] + (uint32_t)((bq ^ b_sw[ntp]) << 4);
                LDSM4(bh[ntp], addr);
                LDSM4(bl[ntp], addr + BPL);
            }
            // pass 1: ah * bh
            #pragma unroll
            for (int mt = 0; mt < 4; ++mt)
                #pragma unroll
                for (int nt = 0; nt < 8; ++nt)
                    mma16816(acc[mt][nt], ah[mt], &bh[nt >> 1][(nt & 1) * 2]);
            // load al while pass2 runs
            #pragma unroll
            for (int mt = 0; mt < 4; ++mt)
                LDSM4(al[mt], Ab + a_row[mt] + (uint32_t)((aq ^ a_sw[mt]) << 4) + APL);
            // pass 2: ah * bl
            #pragma unroll
            for (int mt = 0; mt < 4; ++mt)
                #pragma unroll
                for (int nt = 0; nt < 8; ++nt)
                    mma16816(acc[mt][nt], ah[mt], &bl[nt >> 1][(nt & 1) * 2]);
            // pass 3: al * bh
            #pragma unroll
            for (int mt = 0; mt < 4; ++mt)
                #pragma unroll
                for (int nt = 0; nt < 8; ++nt)
                    mma16816(acc[mt][nt], al[mt], &bh[nt >> 1][(nt & 1) * 2]);
        }
    }

    // ---------------- epilogue ----------------
    if (G.omode != 2) {
        #pragma unroll
        for (int nt = 0; nt < 8; ++nt) {
            int col = wn + nt * 8 + tq * 2;
            float2 bv = *(const float2*)(G.bias + col);
            #pragma unroll
            for (int mt = 0; mt < 4; ++mt) {
                int r0 = tok0 + wm + mt * 16 + g;
                float o00 = actf(acc[mt][nt][0] + bv.x, G.act);
                float o01 = actf(acc[mt][nt][1] + bv.y, G.act);
                float o10 = actf(acc[mt][nt][2] + bv.x, G.act);
                float o11 = actf(acc[mt][nt][3] + bv.y, G.act);
                if (G.omode == 0) {
                    *(float2*)(G.outf + (size_t)r0 * G.ldo + G.ocol + col)     = make_float2(o00, o01);
                    *(float2*)(G.outf + (size_t)(r0+8) * G.ldo + G.ocol + col) = make_float2(o10, o11);
                } else {
                    *(uint32_t*)(G.oh + (size_t)r0 * G.ldob + G.ocolb + col)     = pack_hi(o00, o01);
                    *(uint32_t*)(G.ol + (size_t)r0 * G.ldob + G.ocolb + col)     = pack_lo(o00, o01);
                    *(uint32_t*)(G.oh + (size_t)(r0+8) * G.ldob + G.ocolb + col) = pack_hi(o10, o11);
                    *(uint32_t*)(G.ol + (size_t)(r0+8) * G.ldob + G.ocolb + col) = pack_lo(o10, o11);
                }
            }
        }
    } else {
        float p0[4] = {0,0,0,0}, p1[4] = {0,0,0,0};
        #pragma unroll
        for (int nt = 0; nt < 8; ++nt) {
            int col = wn + nt * 8 + tq * 2;
            float2 bv = *(const float2*)(G.bias + col);
            float2 wv = *(const float2*)(G.w2 + G.ocol + col);
            #pragma unroll
            for (int mt = 0; mt < 4; ++mt) {
                float o00 = actf(acc[mt][nt][0] + bv.x, G.act);
                float o01 = actf(acc[mt][nt][1] + bv.y, G.act);
                float o10 = actf(acc[mt][nt][2] + bv.x, G.act);
                float o11 = actf(acc[mt][nt][3] + bv.y, G.act);
                p0[mt] += o00 * wv.x + o01 * wv.y;
                p1[mt] += o10 * wv.x + o11 * wv.y;
            }
        }
        #pragma unroll
        for (int mt = 0; mt < 4; ++mt) {
            p0[mt] += __shfl_xor_sync(0xffffffffu, p0[mt], 1);
            p0[mt] += __shfl_xor_sync(0xffffffffu, p0[mt], 2);
            p1[mt] += __shfl_xor_sync(0xffffffffu, p1[mt], 1);
            p1[mt] += __shfl_xor_sync(0xffffffffu, p1[mt], 2);
        }
        float* red = (float*)smw;
        __syncthreads();
        if (tq == 0) {
            #pragma unroll
            for (int mt = 0; mt < 4; ++mt) {
                int r = wm + mt * 16 + g;
                red[r * 2 + (wid >> 1)]       = p0[mt];
                red[(r + 8) * 2 + (wid >> 1)] = p1[mt];
            }
        }
        __syncthreads();
        G.pout[tok0 + tid] = red[tid * 2] + red[tid * 2 + 1];
    }
}

// ---------------- DKVMN scan ----------------
__global__ __launch_bounds__(256) void scan_kernel(const float* __restrict__ ivm)
{
    int b   = blockIdx.x;
    int dh  = blockIdx.y * 64;
    int tid = threadIdx.x;
    int dl  = tid >> 2, mq = tid & 3;
    int d   = dh + dl;
    size_t tb = (size_t)b * S;

    float Mv[8];
    #pragma unroll
    for (int m = 0; m < 8; ++m)
        Mv[m] = ivm[(mq * 8 + m) * 128 + d];

    __shared__ float wsm[2][4][32];

    float e[4], a[4];
    if (tid < 128)
        wsm[0][tid >> 5][tid & 31] = g_w[(tb + (tid >> 5)) * 32 + (tid & 31)];
    #pragma unroll
    for (int s = 0; s < 4; ++s) {
        e[s] = g_erase[(tb + s) * 128 + d];
        a[s] = g_add  [(tb + s) * 128 + d];
    }
    __syncthreads();

    for (int gg = 0; gg < S / 4; ++gg) {
        int cur = gg & 1, nxt = cur ^ 1;
        int sbase = gg * 4;
        float en[4], an[4];
        if (gg + 1 < S / 4) {
            if (tid < 128)
                wsm[nxt][tid >> 5][tid & 31] = g_w[(tb + sbase + 4 + (tid >> 5)) * 32 + (tid & 31)];
            #pragma unroll
            for (int s = 0; s < 4; ++s) {
                en[s] = g_erase[(tb + sbase + 4 + s) * 128 + d];
                an[s] = g_add  [(tb + sbase + 4 + s) * 128 + d];
            }
        } else {
            #pragma unroll
            for (int s = 0; s < 4; ++s) { en[s] = 0.f; an[s] = 0.f; }
        }

        #pragma unroll
        for (int s = 0; s < 4; ++s) {
            float r = 0.f;
            #pragma unroll
            for (int m = 0; m < 8; ++m) {
                float wm = wsm[cur][s][mq * 8 + m];
                r = fmaf(wm, Mv[m], r);                        // read BEFORE write
                Mv[m] = fmaf(wm, fmaf(-Mv[m], e[s], a[s]), Mv[m]);
            }
            r += __shfl_xor_sync(0xffffffffu, r, 1);
            r += __shfl_xor_sync(0xffffffffu, r, 2);
            if (mq == 0) {
                __nv_bfloat16 h = __float2bfloat16(r);
                g_rd_h[(tb + sbase + s) * 128 + d] = h;
                g_rd_l[(tb + sbase + s) * 128 + d] = __float2bfloat16(r - __bfloat162float(h));
            }
        }
        __syncthreads();
        #pragma unroll
        for (int s = 0; s < 4; ++s) { e[s] = en[s]; a[s] = an[s]; }
    }
}

// ---------------- combine heads ----------------
__global__ __launch_bounds__(256) void combine_kernel(
    const float* __restrict__ b_ab2, const float* __restrict__ b_df2,
    float* __restrict__ out)
{
    int t = blockIdx.x * 256 + threadIdx.x;
    float pa = g_pa[t] + g_pa[(size_t)T + t] + b_ab2[0];
    float pd = g_pd[t] + b_df2[0];
    float z    = 3.0f * pa - pd;
    float pred = 1.f / (1.f + expf(-z));
    out[t]               = pred;
    out[(size_t)T + t]   = pa;
    out[(size_t)2*T + t] = pd;
    out[(size_t)3*T + t] = z;
}

// ---------------- host launch ----------------
extern "C" void kernel_launch(void* const* d_in, const int* in_sizes, int n_in,
                              void* d_out, int out_size)
{
    const int*   q_data   = (const int*)  d_in[0];
    const int*   qa_data  = (const int*)  d_in[1];
    const float* q_table  = (const float*)d_in[2];
    const float* qa_table = (const float*)d_in[3];
    const float* key_mem  = (const float*)d_in[4];
    const float* init_vm  = (const float*)d_in[5];
    const float* W_erase  = (const float*)d_in[6];
    const float* b_erase  = (const float*)d_in[7];
    const float* W_add    = (const float*)d_in[8];
    const float* b_add    = (const float*)d_in[9];
    const float* W_sum    = (const float*)d_in[10];
    const float* b_sum    = (const float*)d_in[11];
    const float* W_ab1    = (const float*)d_in[12];
    const float* b_ab1    = (const float*)d_in[13];
    const float* W_ab2    = (const float*)d_in[14];
    const float* b_ab2    = (const float*)d_in[15];
    const float* W_df1    = (const float*)d_in[16];
    const float* b_df1    = (const float*)d_in[17];
    const float* W_df2    = (const float*)d_in[18];
    const float* b_df2    = (const float*)d_in[19];
    float* out = (float*)d_out;

    float *pw, *per, *pad, *ppa, *ppd;
    __nv_bfloat16 *qeh, *qel, *qah, *qal, *rdh, *rdl, *smh, *sml;
    __nv_bfloat16 *Weh, *Wel, *Wah, *Wal, *Wdh, *Wdl, *Wsh, *Wsl, *Wbh, *Wbl;
    cudaGetSymbolAddress((void**)&pw,  g_w);
    cudaGetSymbolAddress((void**)&per, g_erase);
    cudaGetSymbolAddress((void**)&pad, g_add);
    cudaGetSymbolAddress((void**)&ppa, g_pa);
    cudaGetSymbolAddress((void**)&ppd, g_pd);
    cudaGetSymbolAddress((void**)&qeh, g_qe_h); cudaGetSymbolAddress((void**)&qel, g_qe_l);
    cudaGetSymbolAddress((void**)&qah, g_qa_h); cudaGetSymbolAddress((void**)&qal, g_qa_l);
    cudaGetSymbolAddress((void**)&rdh, g_rd_h); cudaGetSymbolAddress((void**)&rdl, g_rd_l);
    cudaGetSymbolAddress((void**)&smh, g_sm_h); cudaGetSymbolAddress((void**)&sml, g_sm_l);
    cudaGetSymbolAddress((void**)&Weh, g_We_h); cudaGetSymbolAddress((void**)&Wel, g_We_l);
    cudaGetSymbolAddress((void**)&Wah, g_Wa_h); cudaGetSymbolAddress((void**)&Wal, g_Wa_l);
    cudaGetSymbolAddress((void**)&Wdh, g_Wd_h); cudaGetSymbolAddress((void**)&Wdl, g_Wd_l);
    cudaGetSymbolAddress((void**)&Wsh, g_Ws_h); cudaGetSymbolAddress((void**)&Wsl, g_Ws_l);
    cudaGetSymbolAddress((void**)&Wbh, g_Wb_h); cudaGetSymbolAddress((void**)&Wbl, g_Wb_l);

    cudaFuncSetAttribute(mma_gemm, cudaFuncAttributeMaxDynamicSharedMemorySize, GSM);

    const int MT = T / 128;

    prep_weight_all<<<704, 256>>>(W_erase, W_add, W_df1, W_sum, W_ab1);
    prep_gather_qa<<<T / 8, 256>>>(qa_data, qa_table);
    attn_kernel<<<T / 8, 256>>>(q_data, q_table, key_mem, pw);

    // erase / add / df1(+df2 dot) fused (K=128)
    GDesc Ge = { qah, qal, 128, 0,  nullptr, nullptr, 0, 0,
                 Weh, Wel, 128, 0,  b_erase, 1, 0, per, 128, 0,
                 nullptr, nullptr, 0, 0,  nullptr, nullptr };
    GDesc Ga = { qah, qal, 128, 0,  nullptr, nullptr, 0, 0,
                 Wah, Wal, 128, 0,  b_add,   2, 0, pad, 128, 0,
                 nullptr, nullptr, 0, 0,  nullptr, nullptr };
    GDesc Gd = { qeh, qel, 128, 0,  nullptr, nullptr, 0, 0,
                 Wdh, Wdl, 128, 0,  b_df1,   2, 2, nullptr, 0, 0,
                 nullptr, nullptr, 0, 0,  W_df2, ppd };
    mma_gemm<<<dim3(MT, 3), 128, GSM>>>(128, Ge, Ga, Gd);

    scan_kernel<<<dim3(B, 2), 256>>>(init_vm);

    // summary = tanh([reads | qe] @ W_sum + b), K=256, bf16 hi/lo out
    GDesc Gs0 = { rdh, rdl, 128, 0,  qeh, qel, 128, 0,
                  Wsh, Wsl, 256, 0,    b_sum,       2, 1, nullptr, 0, 0,
                  smh, sml, 256, 0,    nullptr, nullptr };
    GDesc Gs1 = { rdh, rdl, 128, 0,  qeh, qel, 128, 0,
                  Wsh, Wsl, 256, 128,  b_sum + 128, 2, 1, nullptr, 0, 0,
                  smh, sml, 256, 128,  nullptr, nullptr };
    mma_gemm<<<dim3(MT, 2), 128, GSM>>>(256, Gs0, Gs1, Gs1);

    // ability hidden + head dot (K=256, dot-reduce per N-half)
    GDesc Gb0 = { smh, sml, 256, 0,  smh, sml, 256, 128,
                  Wbh, Wbl, 256, 0,    b_ab1,       2, 2, nullptr, 0, 0,
                  nullptr, nullptr, 0, 0,  W_ab2, ppa };
    GDesc Gb1 = { smh, sml, 256, 0,  smh, sml, 256, 128,
                  Wbh, Wbl, 256, 128,  b_ab1 + 128, 2, 2, nullptr, 0, 128,
                  nullptr, nullptr, 0, 0,  W_ab2, ppa + T };
    mma_gemm<<<dim3(MT, 2), 128, GSM>>>(256, Gb0, Gb1, Gb1);

    combine_kernel<<<T / 256, 256>>>(b_ab2, b_df2, out);
}

// round 14
// speedup vs baseline: 1.5428x; 1.5428x over previous
#include <cuda_runtime.h>
#include <cuda_bf16.h>
#include <math.h>
#include <stdint.h>

constexpr int B   = 256;
constexpr int S   = 512;
constexpr int T   = B * S;       // 131072 tokens
constexpr int MEM = 32;
constexpr int DK  = 128;
constexpr int DV  = 128;
constexpr int DS  = 256;

// ---------------- scratch ----------------
__device__ float g_w    [(size_t)T * MEM];
__device__ float g_erase[(size_t)T * DV];
__device__ float g_add  [(size_t)T * DV];
__device__ float g_pa   [(size_t)2 * T];
__device__ float g_pd   [(size_t)T];

__device__ __nv_bfloat16 g_qe_h[(size_t)T * 128], g_qe_l[(size_t)T * 128];
__device__ __nv_bfloat16 g_qa_h[(size_t)T * 128], g_qa_l[(size_t)T * 128];
__device__ __nv_bfloat16 g_rd_h[(size_t)T * 128], g_rd_l[(size_t)T * 128];
__device__ __nv_bfloat16 g_sm_h[(size_t)T * 256], g_sm_l[(size_t)T * 256];

__device__ __nv_bfloat16 g_We_h[128*128], g_We_l[128*128];
__device__ __nv_bfloat16 g_Wa_h[128*128], g_Wa_l[128*128];
__device__ __nv_bfloat16 g_Wd_h[128*128], g_Wd_l[128*128];
__device__ __nv_bfloat16 g_Ws_h[256*256], g_Ws_l[256*256];
__device__ __nv_bfloat16 g_Wb_h[256*256], g_Wb_l[256*256];

__device__ __forceinline__ float actf(float x, int a) {
    if (a == 1) return 1.f / (1.f + expf(-x));
    if (a == 2) return tanhf(x);
    return x;
}
__device__ __forceinline__ uint32_t pack_hi(float x, float y) {
    __nv_bfloat16 hx = __float2bfloat16(x);
    __nv_bfloat16 hy = __float2bfloat16(y);
    return ((uint32_t)__bfloat16_as_ushort(hy) << 16) | __bfloat16_as_ushort(hx);
}
__device__ __forceinline__ uint32_t pack_lo(float x, float y) {
    __nv_bfloat16 hx = __float2bfloat16(x);
    __nv_bfloat16 hy = __float2bfloat16(y);
    __nv_bfloat16 lx = __float2bfloat16(x - __bfloat162float(hx));
    __nv_bfloat16 ly = __float2bfloat16(y - __bfloat162float(hy));
    return ((uint32_t)__bfloat16_as_ushort(ly) << 16) | __bfloat16_as_ushort(lx);
}

// ---------------- prep: all 5 weights, one launch ----------------
__global__ __launch_bounds__(256) void prep_weight_all(
    const float* __restrict__ W0, const float* __restrict__ W1,
    const float* __restrict__ W2, const float* __restrict__ W3,
    const float* __restrict__ W4)
{
    int bid = blockIdx.x;
    const float* W; __nv_bfloat16 *th, *tl; int K, N, base;
    if (bid < 64)       { W = W0; th = g_We_h; tl = g_We_l; K = 128; N = 128; base = 0; }
    else if (bid < 128) { W = W1; th = g_Wa_h; tl = g_Wa_l; K = 128; N = 128; base = 64; }
    else if (bid < 192) { W = W2; th = g_Wd_h; tl = g_Wd_l; K = 128; N = 128; base = 128; }
    else if (bid < 448) { W = W3; th = g_Ws_h; tl = g_Ws_l; K = 256; N = 256; base = 192; }
    else                { W = W4; th = g_Wb_h; tl = g_Wb_l; K = 256; N = 256; base = 448; }
    int e = (bid - base) * 256 + threadIdx.x;
    int k = e / N, n = e - k * N;
    float v = W[e];
    __nv_bfloat16 h = __float2bfloat16(v);
    th[(size_t)n * K + k] = h;
    tl[(size_t)n * K + k] = __float2bfloat16(v - __bfloat162float(h));
}

// ---------------- prep: qa gather + fp32 -> bf16 hi/lo ----------------
__global__ __launch_bounds__(256) void prep_gather_qa(
    const int* __restrict__ qa_data, const float* __restrict__ qa_table)
{
    int t    = blockIdx.x * 8 + (threadIdx.x >> 5);
    int lane = threadIdx.x & 31;
    int row = qa_data[t];
    float4 v = *(const float4*)(qa_table + (size_t)row * 128 + lane * 4);
    uint2 h, l;
    h.x = pack_hi(v.x, v.y); h.y = pack_hi(v.z, v.w);
    l.x = pack_lo(v.x, v.y); l.y = pack_lo(v.z, v.w);
    *(uint2*)(g_qa_h + (size_t)t * 128 + lane * 4) = h;
    *(uint2*)(g_qa_l + (size_t)t * 128 + lane * 4) = l;
}

// ---------------- attention softmax + qe bf16 conversion ----------------
__global__ __launch_bounds__(256) void attn_kernel(
    const int* __restrict__ q_data,
    const float* __restrict__ q_table,
    const float* __restrict__ key_memory,
    float* __restrict__ w_out)
{
    __shared__ float ksm[32 * 129];
    int tid = threadIdx.x;
    for (int i = tid; i < 32 * 128; i += 256) {
        int m = i >> 7, k = i & 127;
        ksm[m * 129 + k] = key_memory[i];
    }
    __syncthreads();

    int warp = tid >> 5, lane = tid & 31;
    int t = blockIdx.x * 8 + warp;
    int row = q_data[t];

    float4 v = *(const float4*)(q_table + (size_t)row * 128 + lane * 4);
    uint2 hh, ll;
    hh.x = pack_hi(v.x, v.y); hh.y = pack_hi(v.z, v.w);
    ll.x = pack_lo(v.x, v.y); ll.y = pack_lo(v.z, v.w);
    *(uint2*)(g_qe_h + (size_t)t * 128 + lane * 4) = hh;
    *(uint2*)(g_qe_l + (size_t)t * 128 + lane * 4) = ll;

    float lg = 0.f;
    #pragma unroll
    for (int k = 0; k < 128; ++k) {
        float comp = ((k & 3) == 0) ? v.x : ((k & 3) == 1) ? v.y : ((k & 3) == 2) ? v.z : v.w;
        float qv = __shfl_sync(0xffffffffu, comp, k >> 2);
        lg = fmaf(qv, ksm[lane * 129 + k], lg);
    }
    float mx = lg;
    #pragma unroll
    for (int off = 16; off > 0; off >>= 1)
        mx = fmaxf(mx, __shfl_xor_sync(0xffffffffu, mx, off));
    float e = expf(lg - mx);
    float sum = e;
    #pragma unroll
    for (int off = 16; off > 0; off >>= 1)
        sum += __shfl_xor_sync(0xffffffffu, sum, off);
    w_out[(size_t)t * 32 + lane] = e / sum;
}

// ---------------- bf16x3 GEMM: B-resident, 3-stage A ring, 1 sync/chunk ----------------
// (byte-identical to the R9 kernel that measured 831 us / 128 regs, no spill)
struct GDesc {
    const __nv_bfloat16 *a0h, *a0l; int p0, o0;
    const __nv_bfloat16 *a1h, *a1l; int p1, o1;
    const __nv_bfloat16 *wh, *wl;   int ldk, wcol;
    const float* bias;
    int act;
    int omode;      // 0 fp32 store, 1 bf16 hi/lo store, 2 dot-reduce (no store)
    float* outf; int ldo, ocol;
    __nv_bfloat16 *oh, *ol; int ldob, ocolb;
    const float* w2;
    float* pout;
};

__device__ __forceinline__ void mma16816(float* c, const uint32_t* a, const uint32_t* b) {
    asm volatile(
        "mma.sync.aligned.m16n8k16.row.col.f32.bf16.bf16.f32 "
        "{%0,%1,%2,%3}, {%4,%5,%6,%7}, {%8,%9}, {%0,%1,%2,%3};"
        : "+f"(c[0]), "+f"(c[1]), "+f"(c[2]), "+f"(c[3])
        : "r"(a[0]), "r"(a[1]), "r"(a[2]), "r"(a[3]), "r"(b[0]), "r"(b[1]));
}
#define LDSM4(r, addr) \
    asm volatile("ldmatrix.sync.aligned.m8n8.x4.shared.b16 {%0,%1,%2,%3}, [%4];" \
        : "=r"((r)[0]), "=r"((r)[1]), "=r"((r)[2]), "=r"((r)[3]) : "r"(addr))

__device__ __forceinline__ void cpa16(uint32_t dst, const void* src) {
    asm volatile("cp.async.cg.shared.global [%0], [%1], 16;" :: "r"(dst), "l"(src));
}

constexpr int APL  = 8192;
constexpr int AST  = 2 * APL;
constexpr int BPL  = 32768;
constexpr int AOFF = 2 * BPL;
constexpr int GSM  = AOFF + 3 * AST; // 114688 -> 2 CTAs/SM

__device__ __forceinline__ void prefetch_A(const GDesc& G, int tok0, int c,
                                           uint32_t stage_base, int tid)
{
    int kbase = c << 5;
    const __nv_bfloat16 *Ah, *Al; int Ap, Ao;
    if (kbase < 128) { Ah = G.a0h; Al = G.a0l; Ap = G.p0; Ao = G.o0 + kbase; }
    else             { Ah = G.a1h; Al = G.a1l; Ap = G.p1; Ao = G.o1 + kbase - 128; }
    #pragma unroll
    for (int j = 0; j < 2; ++j) {
        int e = tid + j * 256;
        int r = e >> 2, q = e & 3;
        int qs = q ^ ((r >> 1) & 3);
        size_t src = (size_t)(tok0 + r) * Ap + Ao + q * 8;
        uint32_t dst = stage_base + (uint32_t)(r * 64 + qs * 16);
        cpa16(dst,       Ah + src);
        cpa16(dst + APL, Al + src);
    }
}

__device__ __forceinline__ void load_B(const GDesc& G, int khalf, uint32_t sbase, int tid)
{
    #pragma unroll
    for (int j = 0; j < 8; ++j) {
        int e = tid + j * 256;
        int n = e >> 4, q = e & 15;
        int qs = q ^ (n & 7);
        size_t src = (size_t)(G.wcol + n) * G.ldk + khalf + q * 8;
        uint32_t dst = sbase + (uint32_t)(n * 256 + qs * 16);
        cpa16(dst,       G.wh + src);
        cpa16(dst + BPL, G.wl + src);
    }
}

__global__ __launch_bounds__(256, 2) void mma_gemm(int Ktot, GDesc G0, GDesc G1, GDesc G2)
{
    extern __shared__ __align__(16) uint32_t smw[];
    uint32_t sbase = (uint32_t)__cvta_generic_to_shared(smw);

    const GDesc G = (blockIdx.y == 0) ? G0 : ((blockIdx.y == 1) ? G1 : G2);

    int tid  = threadIdx.x;
    int wid  = tid >> 5, lane = tid & 31;
    int g    = lane >> 2, tq = lane & 3;
    int tok0 = blockIdx.x * 128;

    int wm = (wid & 1) * 64;
    int wn = (wid >> 1) * 32;

    int lane_r = lane & 15;
    int a_qb   = lane >> 4;
    int jb     = lane >> 3;
    uint32_t a_row[4]; int a_sw[4];
    #pragma unroll
    for (int mt = 0; mt < 4; ++mt) {
        int r = wm + mt * 16 + lane_r;
        a_row[mt] = (uint32_t)(r * 64);
        a_sw[mt]  = (r >> 1) & 3;
    }
    uint32_t b_row[2]; int b_sw[2];
    #pragma unroll
    for (int ntp = 0; ntp < 2; ++ntp) {
        int n = wn + ntp * 16 + ((jb >> 1) * 8) + (lane & 7);
        b_row[ntp] = (uint32_t)(n * 256);
        b_sw[ntp]  = n & 7;
    }
    int b_qb = jb & 1;

    float acc[4][4][4];
    #pragma unroll
    for (int i = 0; i < 4; ++i)
        #pragma unroll
        for (int j = 0; j < 4; ++j)
            #pragma unroll
            for (int u = 0; u < 4; ++u) acc[i][j][u] = 0.f;

    int nch = Ktot >> 5;

    load_B(G, 0, sbase, tid);
    prefetch_A(G, tok0, 0, sbase + AOFF, tid);
    asm volatile("cp.async.commit_group;");
    if (nch > 1) prefetch_A(G, tok0, 1, sbase + AOFF + AST, tid);
    asm volatile("cp.async.commit_group;");

    for (int c = 0; c < nch; ++c) {
        asm volatile("cp.async.wait_group 1;");
        __syncthreads();
        if (c == 4) {                         // only when nch == 8: B swap
            load_B(G, 128, sbase, tid);
            if (c + 2 < nch) {
                int s = (c + 2) % 3;
                prefetch_A(G, tok0, c + 2, sbase + AOFF + (uint32_t)s * AST, tid);
            }
            asm volatile("cp.async.commit_group;");
            asm volatile("cp.async.wait_group 0;");
            __syncthreads();
        } else {
            if (c + 2 < nch) {
                int s = (c + 2) % 3;
                prefetch_A(G, tok0, c + 2, sbase + AOFF + (uint32_t)s * AST, tid);
            }
            asm volatile("cp.async.commit_group;");
        }

        uint32_t Ab = sbase + AOFF + (uint32_t)(c % 3) * AST;
        int bq_c = (c & 3) * 4 + b_qb;

        #pragma unroll
        for (int h = 0; h < 2; ++h) {
            uint32_t ah[4][4], al[4][4], bh[2][4], bl[2][4];
            int aq = h * 2 + a_qb;
            #pragma unroll
            for (int mt = 0; mt < 4; ++mt) {
                uint32_t addr = Ab + a_row[mt] + (uint32_t)((aq ^ a_sw[mt]) << 4);
                LDSM4(ah[mt], addr);
                LDSM4(al[mt], addr + APL);
            }
            int bq = bq_c + h * 2;
            #pragma unroll
            for (int ntp = 0; ntp < 2; ++ntp) {
                uint32_t addr = sbase + b_row[ntp] + (uint32_t)((bq ^ b_sw[ntp]) << 4);
                LDSM4(bh[ntp], addr);
                LDSM4(bl[ntp], addr + BPL);
            }
            #pragma unroll
            for (int mt = 0; mt < 4; ++mt)
                #pragma unroll
                for (int nt = 0; nt < 4; ++nt)
                    mma16816(acc[mt][nt], ah[mt], &bh[nt >> 1][(nt & 1) * 2]);
            #pragma unroll
            for (int mt = 0; mt < 4; ++mt)
                #pragma unroll
                for (int nt = 0; nt < 4; ++nt)
                    mma16816(acc[mt][nt], ah[mt], &bl[nt >> 1][(nt & 1) * 2]);
            #pragma unroll
            for (int mt = 0; mt < 4; ++mt)
                #pragma unroll
                for (int nt = 0; nt < 4; ++nt)
                    mma16816(acc[mt][nt], al[mt], &bh[nt >> 1][(nt & 1) * 2]);
        }
    }

    // ---------------- epilogue ----------------
    if (G.omode != 2) {
        #pragma unroll
        for (int nt = 0; nt < 4; ++nt) {
            int col = wn + nt * 8 + tq * 2;
            float2 bv = *(const float2*)(G.bias + col);
            #pragma unroll
            for (int mt = 0; mt < 4; ++mt) {
                int r0 = tok0 + wm + mt * 16 + g;
                float o00 = actf(acc[mt][nt][0] + bv.x, G.act);
                float o01 = actf(acc[mt][nt][1] + bv.y, G.act);
                float o10 = actf(acc[mt][nt][2] + bv.x, G.act);
                float o11 = actf(acc[mt][nt][3] + bv.y, G.act);
                if (G.omode == 0) {
                    *(float2*)(G.outf + (size_t)r0 * G.ldo + G.ocol + col)     = make_float2(o00, o01);
                    *(float2*)(G.outf + (size_t)(r0+8) * G.ldo + G.ocol + col) = make_float2(o10, o11);
                } else {
                    *(uint32_t*)(G.oh + (size_t)r0 * G.ldob + G.ocolb + col)     = pack_hi(o00, o01);
                    *(uint32_t*)(G.ol + (size_t)r0 * G.ldob + G.ocolb + col)     = pack_lo(o00, o01);
                    *(uint32_t*)(G.oh + (size_t)(r0+8) * G.ldob + G.ocolb + col) = pack_hi(o10, o11);
                    *(uint32_t*)(G.ol + (size_t)(r0+8) * G.ldob + G.ocolb + col) = pack_lo(o10, o11);
                }
            }
        }
    } else {
        float p0[4] = {0,0,0,0}, p1[4] = {0,0,0,0};
        #pragma unroll
        for (int nt = 0; nt < 4; ++nt) {
            int col = wn + nt * 8 + tq * 2;
            float2 bv = *(const float2*)(G.bias + col);
            float2 wv = *(const float2*)(G.w2 + G.ocol + col);
            #pragma unroll
            for (int mt = 0; mt < 4; ++mt) {
                float o00 = actf(acc[mt][nt][0] + bv.x, G.act);
                float o01 = actf(acc[mt][nt][1] + bv.y, G.act);
                float o10 = actf(acc[mt][nt][2] + bv.x, G.act);
                float o11 = actf(acc[mt][nt][3] + bv.y, G.act);
                p0[mt] += o00 * wv.x + o01 * wv.y;
                p1[mt] += o10 * wv.x + o11 * wv.y;
            }
        }
        #pragma unroll
        for (int mt = 0; mt < 4; ++mt) {
            p0[mt] += __shfl_xor_sync(0xffffffffu, p0[mt], 1);
            p0[mt] += __shfl_xor_sync(0xffffffffu, p0[mt], 2);
            p1[mt] += __shfl_xor_sync(0xffffffffu, p1[mt], 1);
            p1[mt] += __shfl_xor_sync(0xffffffffu, p1[mt], 2);
        }
        float* red = (float*)smw;
        __syncthreads();
        if (tq == 0) {
            #pragma unroll
            for (int mt = 0; mt < 4; ++mt) {
                int r = wm + mt * 16 + g;
                red[r * 4 + (wid >> 1)]       = p0[mt];
                red[(r + 8) * 4 + (wid >> 1)] = p1[mt];
            }
        }
        __syncthreads();
        if (tid < 128)
            G.pout[tok0 + tid] = red[tid*4] + red[tid*4+1] + red[tid*4+2] + red[tid*4+3];
    }
}

// ---------------- DKVMN scan: 8-step prefetch groups ----------------
__global__ __launch_bounds__(256) void scan_kernel(const float* __restrict__ ivm)
{
    int b   = blockIdx.x;
    int dh  = blockIdx.y * 64;
    int tid = threadIdx.x;
    int dl  = tid >> 2, mq = tid & 3;
    int d   = dh + dl;
    size_t tb = (size_t)b * S;

    float Mv[8];
    #pragma unroll
    for (int m = 0; m < 8; ++m)
        Mv[m] = ivm[(mq * 8 + m) * 128 + d];

    __shared__ float wsm[2][8][32];

    float e[8], a[8];
    // preload group 0: 8 steps of w (256 values -> all 256 threads), e, a
    wsm[0][tid >> 5][tid & 31] = g_w[(tb + (tid >> 5)) * 32 + (tid & 31)];
    #pragma unroll
    for (int s = 0; s < 8; ++s) {
        e[s] = g_erase[(tb + s) * 128 + d];
        a[s] = g_add  [(tb + s) * 128 + d];
    }
    __syncthreads();

    for (int gg = 0; gg < S / 8; ++gg) {
        int cur = gg & 1, nxt = cur ^ 1;
        int sb = gg * 8;
        float en[8], an[8];
        if (gg + 1 < S / 8) {
            wsm[nxt][tid >> 5][tid & 31] = g_w[(tb + sb + 8 + (tid >> 5)) * 32 + (tid & 31)];
            #pragma unroll
            for (int s = 0; s < 8; ++s) {
                en[s] = g_erase[(tb + sb + 8 + s) * 128 + d];
                an[s] = g_add  [(tb + sb + 8 + s) * 128 + d];
            }
        } else {
            #pragma unroll
            for (int s = 0; s < 8; ++s) { en[s] = 0.f; an[s] = 0.f; }
        }

        #pragma unroll
        for (int s = 0; s < 8; ++s) {
            float r = 0.f;
            #pragma unroll
            for (int m = 0; m < 8; ++m) {
                float wm = wsm[cur][s][mq * 8 + m];
                r = fmaf(wm, Mv[m], r);                        // read BEFORE write
                Mv[m] = fmaf(wm, fmaf(-Mv[m], e[s], a[s]), Mv[m]);
            }
            r += __shfl_xor_sync(0xffffffffu, r, 1);
            r += __shfl_xor_sync(0xffffffffu, r, 2);
            if (mq == 0) {
                __nv_bfloat16 h = __float2bfloat16(r);
                g_rd_h[(tb + sb + s) * 128 + d] = h;
                g_rd_l[(tb + sb + s) * 128 + d] = __float2bfloat16(r - __bfloat162float(h));
            }
        }
        __syncthreads();
        #pragma unroll
        for (int s = 0; s < 8; ++s) { e[s] = en[s]; a[s] = an[s]; }
    }
}

// ---------------- combine heads ----------------
__global__ __launch_bounds__(256) void combine_kernel(
    const float* __restrict__ b_ab2, const float* __restrict__ b_df2,
    float* __restrict__ out)
{
    int t = blockIdx.x * 256 + threadIdx.x;
    float pa = g_pa[t] + g_pa[(size_t)T + t] + b_ab2[0];
    float pd = g_pd[t] + b_df2[0];
    float z    = 3.0f * pa - pd;
    float pred = 1.f / (1.f + expf(-z));
    out[t]               = pred;
    out[(size_t)T + t]   = pa;
    out[(size_t)2*T + t] = pd;
    out[(size_t)3*T + t] = z;
}

// ---------------- host launch ----------------
extern "C" void kernel_launch(void* const* d_in, const int* in_sizes, int n_in,
                              void* d_out, int out_size)
{
    const int*   q_data   = (const int*)  d_in[0];
    const int*   qa_data  = (const int*)  d_in[1];
    const float* q_table  = (const float*)d_in[2];
    const float* qa_table = (const float*)d_in[3];
    const float* key_mem  = (const float*)d_in[4];
    const float* init_vm  = (const float*)d_in[5];
    const float* W_erase  = (const float*)d_in[6];
    const float* b_erase  = (const float*)d_in[7];
    const float* W_add    = (const float*)d_in[8];
    const float* b_add    = (const float*)d_in[9];
    const float* W_sum    = (const float*)d_in[10];
    const float* b_sum    = (const float*)d_in[11];
    const float* W_ab1    = (const float*)d_in[12];
    const float* b_ab1    = (const float*)d_in[13];
    const float* W_ab2    = (const float*)d_in[14];
    const float* b_ab2    = (const float*)d_in[15];
    const float* W_df1    = (const float*)d_in[16];
    const float* b_df1    = (const float*)d_in[17];
    const float* W_df2    = (const float*)d_in[18];
    const float* b_df2    = (const float*)d_in[19];
    float* out = (float*)d_out;

    float *pw, *per, *pad, *ppa, *ppd;
    __nv_bfloat16 *qeh, *qel, *qah, *qal, *rdh, *rdl, *smh, *sml;
    __nv_bfloat16 *Weh, *Wel, *Wah, *Wal, *Wdh, *Wdl, *Wsh, *Wsl, *Wbh, *Wbl;
    cudaGetSymbolAddress((void**)&pw,  g_w);
    cudaGetSymbolAddress((void**)&per, g_erase);
    cudaGetSymbolAddress((void**)&pad, g_add);
    cudaGetSymbolAddress((void**)&ppa, g_pa);
    cudaGetSymbolAddress((void**)&ppd, g_pd);
    cudaGetSymbolAddress((void**)&qeh, g_qe_h); cudaGetSymbolAddress((void**)&qel, g_qe_l);
    cudaGetSymbolAddress((void**)&qah, g_qa_h); cudaGetSymbolAddress((void**)&qal, g_qa_l);
    cudaGetSymbolAddress((void**)&rdh, g_rd_h); cudaGetSymbolAddress((void**)&rdl, g_rd_l);
    cudaGetSymbolAddress((void**)&smh, g_sm_h); cudaGetSymbolAddress((void**)&sml, g_sm_l);
    cudaGetSymbolAddress((void**)&Weh, g_We_h); cudaGetSymbolAddress((void**)&Wel, g_We_l);
    cudaGetSymbolAddress((void**)&Wah, g_Wa_h); cudaGetSymbolAddress((void**)&Wal, g_Wa_l);
    cudaGetSymbolAddress((void**)&Wdh, g_Wd_h); cudaGetSymbolAddress((void**)&Wdl, g_Wd_l);
    cudaGetSymbolAddress((void**)&Wsh, g_Ws_h); cudaGetSymbolAddress((void**)&Wsl, g_Ws_l);
    cudaGetSymbolAddress((void**)&Wbh, g_Wb_h); cudaGetSymbolAddress((void**)&Wbl, g_Wb_l);

    cudaFuncSetAttribute(mma_gemm, cudaFuncAttributeMaxDynamicSharedMemorySize, GSM);

    const int MT = T / 128;

    prep_weight_all<<<704, 256>>>(W_erase, W_add, W_df1, W_sum, W_ab1);
    prep_gather_qa<<<T / 8, 256>>>(qa_data, qa_table);
    attn_kernel<<<T / 8, 256>>>(q_data, q_table, key_mem, pw);

    // erase / add / df1(+df2 dot) fused (K=128)
    GDesc Ge = { qah, qal, 128, 0,  nullptr, nullptr, 0, 0,
                 Weh, Wel, 128, 0,  b_erase, 1, 0, per, 128, 0,
                 nullptr, nullptr, 0, 0,  nullptr, nullptr };
    GDesc Ga = { qah, qal, 128, 0,  nullptr, nullptr, 0, 0,
                 Wah, Wal, 128, 0,  b_add,   2, 0, pad, 128, 0,
                 nullptr, nullptr, 0, 0,  nullptr, nullptr };
    GDesc Gd = { qeh, qel, 128, 0,  nullptr, nullptr, 0, 0,
                 Wdh, Wdl, 128, 0,  b_df1,   2, 2, nullptr, 0, 0,
                 nullptr, nullptr, 0, 0,  W_df2, ppd };
    mma_gemm<<<dim3(MT, 3), 256, GSM>>>(128, Ge, Ga, Gd);

    scan_kernel<<<dim3(B, 2), 256>>>(init_vm);

    // summary = tanh([reads | qe] @ W_sum + b), K=256, bf16 hi/lo out
    GDesc Gs0 = { rdh, rdl, 128, 0,  qeh, qel, 128, 0,
                  Wsh, Wsl, 256, 0,    b_sum,       2, 1, nullptr, 0, 0,
                  smh, sml, 256, 0,    nullptr, nullptr };
    GDesc Gs1 = { rdh, rdl, 128, 0,  qeh, qel, 128, 0,
                  Wsh, Wsl, 256, 128,  b_sum + 128, 2, 1, nullptr, 0, 0,
                  smh, sml, 256, 128,  nullptr, nullptr };
    mma_gemm<<<dim3(MT, 2), 256, GSM>>>(256, Gs0, Gs1, Gs1);

    // ability hidden + head dot (K=256, dot-reduce per N-half)
    GDesc Gb0 = { smh, sml, 256, 0,  smh, sml, 256, 128,
                  Wbh, Wbl, 256, 0,    b_ab1,       2, 2, nullptr, 0, 0,
                  nullptr, nullptr, 0, 0,  W_ab2, ppa };
    GDesc Gb1 = { smh, sml, 256, 0,  smh, sml, 256, 128,
                  Wbh, Wbl, 256, 128,  b_ab1 + 128, 2, 2, nullptr, 0, 128,
                  nullptr, nullptr, 0, 0,  W_ab2, ppa + T };
    mma_gemm<<<dim3(MT, 2), 256, GSM>>>(256, Gb0, Gb1, Gb1);

    combine_kernel<<<T / 256, 256>>>(b_ab2, b_df2, out);
}

// round 16
// speedup vs baseline: 1.5464x; 1.0023x over previous
#include <cuda_runtime.h>
#include <cuda_bf16.h>
#include <math.h>
#include <stdint.h>

constexpr int B   = 256;
constexpr int S   = 512;
constexpr int T   = B * S;       // 131072 tokens
constexpr int MEM = 32;
constexpr int DK  = 128;
constexpr int DV  = 128;
constexpr int DS  = 256;

// ---------------- scratch ----------------
__device__ float g_w    [(size_t)T * MEM];
__device__ float g_erase[(size_t)T * DV];
__device__ float g_add  [(size_t)T * DV];
__device__ float g_pa   [(size_t)2 * T];
__device__ float g_pd   [(size_t)T];

__device__ __nv_bfloat16 g_qe_h[(size_t)T * 128], g_qe_l[(size_t)T * 128];
__device__ __nv_bfloat16 g_qa_h[(size_t)T * 128], g_qa_l[(size_t)T * 128];
__device__ __nv_bfloat16 g_rd_h[(size_t)T * 128], g_rd_l[(size_t)T * 128];
__device__ __nv_bfloat16 g_sm_h[(size_t)T * 256], g_sm_l[(size_t)T * 256];

__device__ __nv_bfloat16 g_We_h[128*128], g_We_l[128*128];
__device__ __nv_bfloat16 g_Wa_h[128*128], g_Wa_l[128*128];
__device__ __nv_bfloat16 g_Wd_h[128*128], g_Wd_l[128*128];
__device__ __nv_bfloat16 g_Ws_h[256*256], g_Ws_l[256*256];
__device__ __nv_bfloat16 g_Wb_h[256*256], g_Wb_l[256*256];

__device__ __forceinline__ float actf(float x, int a) {
    if (a == 1) return 1.f / (1.f + expf(-x));
    if (a == 2) return tanhf(x);
    return x;
}
__device__ __forceinline__ uint32_t pack_hi(float x, float y) {
    __nv_bfloat16 hx = __float2bfloat16(x);
    __nv_bfloat16 hy = __float2bfloat16(y);
    return ((uint32_t)__bfloat16_as_ushort(hy) << 16) | __bfloat16_as_ushort(hx);
}
__device__ __forceinline__ uint32_t pack_lo(float x, float y) {
    __nv_bfloat16 hx = __float2bfloat16(x);
    __nv_bfloat16 hy = __float2bfloat16(y);
    __nv_bfloat16 lx = __float2bfloat16(x - __bfloat162float(hx));
    __nv_bfloat16 ly = __float2bfloat16(y - __bfloat162float(hy));
    return ((uint32_t)__bfloat16_as_ushort(ly) << 16) | __bfloat16_as_ushort(lx);
}

// ---------------- merged front-end: weights prep + qa gather + attn(+qe prep) ----------------
// blocks [0,704): weight transpose/split; [704, 704+16384): qa gather;
// [704+16384, 704+32768): attention softmax + qe conversion.
__global__ __launch_bounds__(256) void prep_all(
    const float* __restrict__ W0, const float* __restrict__ W1,
    const float* __restrict__ W2, const float* __restrict__ W3,
    const float* __restrict__ W4,
    const int* __restrict__ qa_data, const float* __restrict__ qa_table,
    const int* __restrict__ q_data,  const float* __restrict__ q_table,
    const float* __restrict__ key_memory, float* __restrict__ w_out)
{
    __shared__ float ksm[32 * 129];
    int bid = blockIdx.x;
    int tid = threadIdx.x;

    if (bid < 704) {
        // ---- weight prep ----
        const float* W; __nv_bfloat16 *th, *tl; int K, N, base;
        if (bid < 64)       { W = W0; th = g_We_h; tl = g_We_l; K = 128; N = 128; base = 0; }
        else if (bid < 128) { W = W1; th = g_Wa_h; tl = g_Wa_l; K = 128; N = 128; base = 64; }
        else if (bid < 192) { W = W2; th = g_Wd_h; tl = g_Wd_l; K = 128; N = 128; base = 128; }
        else if (bid < 448) { W = W3; th = g_Ws_h; tl = g_Ws_l; K = 256; N = 256; base = 192; }
        else                { W = W4; th = g_Wb_h; tl = g_Wb_l; K = 256; N = 256; base = 448; }
        int e = (bid - base) * 256 + tid;
        int k = e / N, n = e - k * N;
        float v = W[e];
        __nv_bfloat16 h = __float2bfloat16(v);
        th[(size_t)n * K + k] = h;
        tl[(size_t)n * K + k] = __float2bfloat16(v - __bfloat162float(h));
        return;
    }
    bid -= 704;

    if (bid < 16384) {
        // ---- qa gather + split ----
        int t    = bid * 8 + (tid >> 5);
        int lane = tid & 31;
        int row = qa_data[t];
        float4 v = *(const float4*)(qa_table + (size_t)row * 128 + lane * 4);
        uint2 h, l;
        h.x = pack_hi(v.x, v.y); h.y = pack_hi(v.z, v.w);
        l.x = pack_lo(v.x, v.y); l.y = pack_lo(v.z, v.w);
        *(uint2*)(g_qa_h + (size_t)t * 128 + lane * 4) = h;
        *(uint2*)(g_qa_l + (size_t)t * 128 + lane * 4) = l;
        return;
    }
    bid -= 16384;

    // ---- attention softmax + qe conversion ----
    for (int i = tid; i < 32 * 128; i += 256) {
        int m = i >> 7, k = i & 127;
        ksm[m * 129 + k] = key_memory[i];
    }
    __syncthreads();

    int warp = tid >> 5, lane = tid & 31;
    int t = bid * 8 + warp;
    int row = q_data[t];

    float4 v = *(const float4*)(q_table + (size_t)row * 128 + lane * 4);
    uint2 hh, ll;
    hh.x = pack_hi(v.x, v.y); hh.y = pack_hi(v.z, v.w);
    ll.x = pack_lo(v.x, v.y); ll.y = pack_lo(v.z, v.w);
    *(uint2*)(g_qe_h + (size_t)t * 128 + lane * 4) = hh;
    *(uint2*)(g_qe_l + (size_t)t * 128 + lane * 4) = ll;

    float lg = 0.f;
    #pragma unroll
    for (int k = 0; k < 128; ++k) {
        float comp = ((k & 3) == 0) ? v.x : ((k & 3) == 1) ? v.y : ((k & 3) == 2) ? v.z : v.w;
        float qv = __shfl_sync(0xffffffffu, comp, k >> 2);
        lg = fmaf(qv, ksm[lane * 129 + k], lg);
    }
    float mx = lg;
    #pragma unroll
    for (int off = 16; off > 0; off >>= 1)
        mx = fmaxf(mx, __shfl_xor_sync(0xffffffffu, mx, off));
    float e = expf(lg - mx);
    float sum = e;
    #pragma unroll
    for (int off = 16; off > 0; off >>= 1)
        sum += __shfl_xor_sync(0xffffffffu, sum, off);
    w_out[(size_t)t * 32 + lane] = e / sum;
}

// ---------------- bf16x3 GEMM: B-resident, 3-stage A ring, 1 sync/chunk ----------------
// (byte-identical to the R9 kernel: 831 us total, 128 regs, no spill)
struct GDesc {
    const __nv_bfloat16 *a0h, *a0l; int p0, o0;
    const __nv_bfloat16 *a1h, *a1l; int p1, o1;
    const __nv_bfloat16 *wh, *wl;   int ldk, wcol;
    const float* bias;
    int act;
    int omode;      // 0 fp32 store, 1 bf16 hi/lo store, 2 dot-reduce (no store)
    float* outf; int ldo, ocol;
    __nv_bfloat16 *oh, *ol; int ldob, ocolb;
    const float* w2;
    float* pout;
};

__device__ __forceinline__ void mma16816(float* c, const uint32_t* a, const uint32_t* b) {
    asm volatile(
        "mma.sync.aligned.m16n8k16.row.col.f32.bf16.bf16.f32 "
        "{%0,%1,%2,%3}, {%4,%5,%6,%7}, {%8,%9}, {%0,%1,%2,%3};"
        : "+f"(c[0]), "+f"(c[1]), "+f"(c[2]), "+f"(c[3])
        : "r"(a[0]), "r"(a[1]), "r"(a[2]), "r"(a[3]), "r"(b[0]), "r"(b[1]));
}
#define LDSM4(r, addr) \
    asm volatile("ldmatrix.sync.aligned.m8n8.x4.shared.b16 {%0,%1,%2,%3}, [%4];" \
        : "=r"((r)[0]), "=r"((r)[1]), "=r"((r)[2]), "=r"((r)[3]) : "r"(addr))

__device__ __forceinline__ void cpa16(uint32_t dst, const void* src) {
    asm volatile("cp.async.cg.shared.global [%0], [%1], 16;" :: "r"(dst), "l"(src));
}

constexpr int APL  = 8192;
constexpr int AST  = 2 * APL;
constexpr int BPL  = 32768;
constexpr int AOFF = 2 * BPL;
constexpr int GSM  = AOFF + 3 * AST; // 114688 -> 2 CTAs/SM

__device__ __forceinline__ void prefetch_A(const GDesc& G, int tok0, int c,
                                           uint32_t stage_base, int tid)
{
    int kbase = c << 5;
    const __nv_bfloat16 *Ah, *Al; int Ap, Ao;
    if (kbase < 128) { Ah = G.a0h; Al = G.a0l; Ap = G.p0; Ao = G.o0 + kbase; }
    else             { Ah = G.a1h; Al = G.a1l; Ap = G.p1; Ao = G.o1 + kbase - 128; }
    #pragma unroll
    for (int j = 0; j < 2; ++j) {
        int e = tid + j * 256;
        int r = e >> 2, q = e & 3;
        int qs = q ^ ((r >> 1) & 3);
        size_t src = (size_t)(tok0 + r) * Ap + Ao + q * 8;
        uint32_t dst = stage_base + (uint32_t)(r * 64 + qs * 16);
        cpa16(dst,       Ah + src);
        cpa16(dst + APL, Al + src);
    }
}

__device__ __forceinline__ void load_B(const GDesc& G, int khalf, uint32_t sbase, int tid)
{
    #pragma unroll
    for (int j = 0; j < 8; ++j) {
        int e = tid + j * 256;
        int n = e >> 4, q = e & 15;
        int qs = q ^ (n & 7);
        size_t src = (size_t)(G.wcol + n) * G.ldk + khalf + q * 8;
        uint32_t dst = sbase + (uint32_t)(n * 256 + qs * 16);
        cpa16(dst,       G.wh + src);
        cpa16(dst + BPL, G.wl + src);
    }
}

__global__ __launch_bounds__(256, 2) void mma_gemm(int Ktot, GDesc G0, GDesc G1, GDesc G2)
{
    extern __shared__ __align__(16) uint32_t smw[];
    uint32_t sbase = (uint32_t)__cvta_generic_to_shared(smw);

    const GDesc G = (blockIdx.y == 0) ? G0 : ((blockIdx.y == 1) ? G1 : G2);

    int tid  = threadIdx.x;
    int wid  = tid >> 5, lane = tid & 31;
    int g    = lane >> 2, tq = lane & 3;
    int tok0 = blockIdx.x * 128;

    int wm = (wid & 1) * 64;
    int wn = (wid >> 1) * 32;

    int lane_r = lane & 15;
    int a_qb   = lane >> 4;
    int jb     = lane >> 3;
    uint32_t a_row[4]; int a_sw[4];
    #pragma unroll
    for (int mt = 0; mt < 4; ++mt) {
        int r = wm + mt * 16 + lane_r;
        a_row[mt] = (uint32_t)(r * 64);
        a_sw[mt]  = (r >> 1) & 3;
    }
    uint32_t b_row[2]; int b_sw[2];
    #pragma unroll
    for (int ntp = 0; ntp < 2; ++ntp) {
        int n = wn + ntp * 16 + ((jb >> 1) * 8) + (lane & 7);
        b_row[ntp] = (uint32_t)(n * 256);
        b_sw[ntp]  = n & 7;
    }
    int b_qb = jb & 1;

    float acc[4][4][4];
    #pragma unroll
    for (int i = 0; i < 4; ++i)
        #pragma unroll
        for (int j = 0; j < 4; ++j)
            #pragma unroll
            for (int u = 0; u < 4; ++u) acc[i][j][u] = 0.f;

    int nch = Ktot >> 5;

    load_B(G, 0, sbase, tid);
    prefetch_A(G, tok0, 0, sbase + AOFF, tid);
    asm volatile("cp.async.commit_group;");
    if (nch > 1) prefetch_A(G, tok0, 1, sbase + AOFF + AST, tid);
    asm volatile("cp.async.commit_group;");

    for (int c = 0; c < nch; ++c) {
        asm volatile("cp.async.wait_group 1;");
        __syncthreads();
        if (c == 4) {                         // only when nch == 8: B swap
            load_B(G, 128, sbase, tid);
            if (c + 2 < nch) {
                int s = (c + 2) % 3;
                prefetch_A(G, tok0, c + 2, sbase + AOFF + (uint32_t)s * AST, tid);
            }
            asm volatile("cp.async.commit_group;");
            asm volatile("cp.async.wait_group 0;");
            __syncthreads();
        } else {
            if (c + 2 < nch) {
                int s = (c + 2) % 3;
                prefetch_A(G, tok0, c + 2, sbase + AOFF + (uint32_t)s * AST, tid);
            }
            asm volatile("cp.async.commit_group;");
        }

        uint32_t Ab = sbase + AOFF + (uint32_t)(c % 3) * AST;
        int bq_c = (c & 3) * 4 + b_qb;

        #pragma unroll
        for (int h = 0; h < 2; ++h) {
            uint32_t ah[4][4], al[4][4], bh[2][4], bl[2][4];
            int aq = h * 2 + a_qb;
            #pragma unroll
            for (int mt = 0; mt < 4; ++mt) {
                uint32_t addr = Ab + a_row[mt] + (uint32_t)((aq ^ a_sw[mt]) << 4);
                LDSM4(ah[mt], addr);
                LDSM4(al[mt], addr + APL);
            }
            int bq = bq_c + h * 2;
            #pragma unroll
            for (int ntp = 0; ntp < 2; ++ntp) {
                uint32_t addr = sbase + b_row[ntp] + (uint32_t)((bq ^ b_sw[ntp]) << 4);
                LDSM4(bh[ntp], addr);
                LDSM4(bl[ntp], addr + BPL);
            }
            #pragma unroll
            for (int mt = 0; mt < 4; ++mt)
                #pragma unroll
                for (int nt = 0; nt < 4; ++nt)
                    mma16816(acc[mt][nt], ah[mt], &bh[nt >> 1][(nt & 1) * 2]);
            #pragma unroll
            for (int mt = 0; mt < 4; ++mt)
                #pragma unroll
                for (int nt = 0; nt < 4; ++nt)
                    mma16816(acc[mt][nt], ah[mt], &bl[nt >> 1][(nt & 1) * 2]);
            #pragma unroll
            for (int mt = 0; mt < 4; ++mt)
                #pragma unroll
                for (int nt = 0; nt < 4; ++nt)
                    mma16816(acc[mt][nt], al[mt], &bh[nt >> 1][(nt & 1) * 2]);
        }
    }

    // ---------------- epilogue ----------------
    if (G.omode != 2) {
        #pragma unroll
        for (int nt = 0; nt < 4; ++nt) {
            int col = wn + nt * 8 + tq * 2;
            float2 bv = *(const float2*)(G.bias + col);
            #pragma unroll
            for (int mt = 0; mt < 4; ++mt) {
                int r0 = tok0 + wm + mt * 16 + g;
                float o00 = actf(acc[mt][nt][0] + bv.x, G.act);
                float o01 = actf(acc[mt][nt][1] + bv.y, G.act);
                float o10 = actf(acc[mt][nt][2] + bv.x, G.act);
                float o11 = actf(acc[mt][nt][3] + bv.y, G.act);
                if (G.omode == 0) {
                    *(float2*)(G.outf + (size_t)r0 * G.ldo + G.ocol + col)     = make_float2(o00, o01);
                    *(float2*)(G.outf + (size_t)(r0+8) * G.ldo + G.ocol + col) = make_float2(o10, o11);
                } else {
                    *(uint32_t*)(G.oh + (size_t)r0 * G.ldob + G.ocolb + col)     = pack_hi(o00, o01);
                    *(uint32_t*)(G.ol + (size_t)r0 * G.ldob + G.ocolb + col)     = pack_lo(o00, o01);
                    *(uint32_t*)(G.oh + (size_t)(r0+8) * G.ldob + G.ocolb + col) = pack_hi(o10, o11);
                    *(uint32_t*)(G.ol + (size_t)(r0+8) * G.ldob + G.ocolb + col) = pack_lo(o10, o11);
                }
            }
        }
    } else {
        float p0[4] = {0,0,0,0}, p1[4] = {0,0,0,0};
        #pragma unroll
        for (int nt = 0; nt < 4; ++nt) {
            int col = wn + nt * 8 + tq * 2;
            float2 bv = *(const float2*)(G.bias + col);
            float2 wv = *(const float2*)(G.w2 + G.ocol + col);
            #pragma unroll
            for (int mt = 0; mt < 4; ++mt) {
                float o00 = actf(acc[mt][nt][0] + bv.x, G.act);
                float o01 = actf(acc[mt][nt][1] + bv.y, G.act);
                float o10 = actf(acc[mt][nt][2] + bv.x, G.act);
                float o11 = actf(acc[mt][nt][3] + bv.y, G.act);
                p0[mt] += o00 * wv.x + o01 * wv.y;
                p1[mt] += o10 * wv.x + o11 * wv.y;
            }
        }
        #pragma unroll
        for (int mt = 0; mt < 4; ++mt) {
            p0[mt] += __shfl_xor_sync(0xffffffffu, p0[mt], 1);
            p0[mt] += __shfl_xor_sync(0xffffffffu, p0[mt], 2);
            p1[mt] += __shfl_xor_sync(0xffffffffu, p1[mt], 1);
            p1[mt] += __shfl_xor_sync(0xffffffffu, p1[mt], 2);
        }
        float* red = (float*)smw;
        __syncthreads();
        if (tq == 0) {
            #pragma unroll
            for (int mt = 0; mt < 4; ++mt) {
                int r = wm + mt * 16 + g;
                red[r * 4 + (wid >> 1)]       = p0[mt];
                red[(r + 8) * 4 + (wid >> 1)] = p1[mt];
            }
        }
        __syncthreads();
        if (tid < 128)
            G.pout[tok0 + tid] = red[tid*4] + red[tid*4+1] + red[tid*4+2] + red[tid*4+3];
    }
}

// ---------------- DKVMN scan (R9-exact, 4-step groups) ----------------
__global__ __launch_bounds__(256) void scan_kernel(const float* __restrict__ ivm)
{
    int b   = blockIdx.x;
    int dh  = blockIdx.y * 64;
    int tid = threadIdx.x;
    int dl  = tid >> 2, mq = tid & 3;
    int d   = dh + dl;
    size_t tb = (size_t)b * S;

    float Mv[8];
    #pragma unroll
    for (int m = 0; m < 8; ++m)
        Mv[m] = ivm[(mq * 8 + m) * 128 + d];

    __shared__ float wsm[2][4][32];

    float e[4], a[4];
    if (tid < 128)
        wsm[0][tid >> 5][tid & 31] = g_w[(tb + (tid >> 5)) * 32 + (tid & 31)];
    #pragma unroll
    for (int s = 0; s < 4; ++s) {
        e[s] = g_erase[(tb + s) * 128 + d];
        a[s] = g_add  [(tb + s) * 128 + d];
    }
    __syncthreads();

    for (int gg = 0; gg < S / 4; ++gg) {
        int cur = gg & 1, nxt = cur ^ 1;
        int sbase = gg * 4;
        float en[4], an[4];
        if (gg + 1 < S / 4) {
            if (tid < 128)
                wsm[nxt][tid >> 5][tid & 31] = g_w[(tb + sbase + 4 + (tid >> 5)) * 32 + (tid & 31)];
            #pragma unroll
            for (int s = 0; s < 4; ++s) {
                en[s] = g_erase[(tb + sbase + 4 + s) * 128 + d];
                an[s] = g_add  [(tb + sbase + 4 + s) * 128 + d];
            }
        } else {
            #pragma unroll
            for (int s = 0; s < 4; ++s) { en[s] = 0.f; an[s] = 0.f; }
        }

        #pragma unroll
        for (int s = 0; s < 4; ++s) {
            float r = 0.f;
            #pragma unroll
            for (int m = 0; m < 8; ++m) {
                float wm = wsm[cur][s][mq * 8 + m];
                r = fmaf(wm, Mv[m], r);                        // read BEFORE write
                Mv[m] = fmaf(wm, fmaf(-Mv[m], e[s], a[s]), Mv[m]);
            }
            r += __shfl_xor_sync(0xffffffffu, r, 1);
            r += __shfl_xor_sync(0xffffffffu, r, 2);
            if (mq == 0) {
                __nv_bfloat16 h = __float2bfloat16(r);
                g_rd_h[(tb + sbase + s) * 128 + d] = h;
                g_rd_l[(tb + sbase + s) * 128 + d] = __float2bfloat16(r - __bfloat162float(h));
            }
        }
        __syncthreads();
        #pragma unroll
        for (int s = 0; s < 4; ++s) { e[s] = en[s]; a[s] = an[s]; }
    }
}

// ---------------- combine heads ----------------
__global__ __launch_bounds__(256) void combine_kernel(
    const float* __restrict__ b_ab2, const float* __restrict__ b_df2,
    float* __restrict__ out)
{
    int t = blockIdx.x * 256 + threadIdx.x;
    float pa = g_pa[t] + g_pa[(size_t)T + t] + b_ab2[0];
    float pd = g_pd[t] + b_df2[0];
    float z    = 3.0f * pa - pd;
    float pred = 1.f / (1.f + expf(-z));
    out[t]               = pred;
    out[(size_t)T + t]   = pa;
    out[(size_t)2*T + t] = pd;
    out[(size_t)3*T + t] = z;
}

// ---------------- host launch ----------------
extern "C" void kernel_launch(void* const* d_in, const int* in_sizes, int n_in,
                              void* d_out, int out_size)
{
    const int*   q_data   = (const int*)  d_in[0];
    const int*   qa_data  = (const int*)  d_in[1];
    const float* q_table  = (const float*)d_in[2];
    const float* qa_table = (const float*)d_in[3];
    const float* key_mem  = (const float*)d_in[4];
    const float* init_vm  = (const float*)d_in[5];
    const float* W_erase  = (const float*)d_in[6];
    const float* b_erase  = (const float*)d_in[7];
    const float* W_add    = (const float*)d_in[8];
    const float* b_add    = (const float*)d_in[9];
    const float* W_sum    = (const float*)d_in[10];
    const float* b_sum    = (const float*)d_in[11];
    const float* W_ab1    = (const float*)d_in[12];
    const float* b_ab1    = (const float*)d_in[13];
    const float* W_ab2    = (const float*)d_in[14];
    const float* b_ab2    = (const float*)d_in[15];
    const float* W_df1    = (const float*)d_in[16];
    const float* b_df1    = (const float*)d_in[17];
    const float* W_df2    = (const float*)d_in[18];
    const float* b_df2    = (const float*)d_in[19];
    float* out = (float*)d_out;

    float *pw, *per, *pad, *ppa, *ppd;
    __nv_bfloat16 *qeh, *qel, *qah, *qal, *rdh, *rdl, *smh, *sml;
    __nv_bfloat16 *Weh, *Wel, *Wah, *Wal, *Wdh, *Wdl, *Wsh, *Wsl, *Wbh, *Wbl;
    cudaGetSymbolAddress((void**)&pw,  g_w);
    cudaGetSymbolAddress((void**)&per, g_erase);
    cudaGetSymbolAddress((void**)&pad, g_add);
    cudaGetSymbolAddress((void**)&ppa, g_pa);
    cudaGetSymbolAddress((void**)&ppd, g_pd);
    cudaGetSymbolAddress((void**)&qeh, g_qe_h); cudaGetSymbolAddress((void**)&qel, g_qe_l);
    cudaGetSymbolAddress((void**)&qah, g_qa_h); cudaGetSymbolAddress((void**)&qal, g_qa_l);
    cudaGetSymbolAddress((void**)&rdh, g_rd_h); cudaGetSymbolAddress((void**)&rdl, g_rd_l);
    cudaGetSymbolAddress((void**)&smh, g_sm_h); cudaGetSymbolAddress((void**)&sml, g_sm_l);
    cudaGetSymbolAddress((void**)&Weh, g_We_h); cudaGetSymbolAddress((void**)&Wel, g_We_l);
    cudaGetSymbolAddress((void**)&Wah, g_Wa_h); cudaGetSymbolAddress((void**)&Wal, g_Wa_l);
    cudaGetSymbolAddress((void**)&Wdh, g_Wd_h); cudaGetSymbolAddress((void**)&Wdl, g_Wd_l);
    cudaGetSymbolAddress((void**)&Wsh, g_Ws_h); cudaGetSymbolAddress((void**)&Wsl, g_Ws_l);
    cudaGetSymbolAddress((void**)&Wbh, g_Wb_h); cudaGetSymbolAddress((void**)&Wbl, g_Wb_l);

    cudaFuncSetAttribute(mma_gemm, cudaFuncAttributeMaxDynamicSharedMemorySize, GSM);

    const int MT = T / 128;

    // merged front-end: weights + qa gather + attn(+qe) in one launch
    prep_all<<<704 + 2 * (T / 8), 256>>>(
        W_erase, W_add, W_df1, W_sum, W_ab1,
        qa_data, qa_table, q_data, q_table, key_mem, pw);

    // erase / add / df1(+df2 dot) fused (K=128)
    GDesc Ge = { qah, qal, 128, 0,  nullptr, nullptr, 0, 0,
                 Weh, Wel, 128, 0,  b_erase, 1, 0, per, 128, 0,
                 nullptr, nullptr, 0, 0,  nullptr, nullptr };
    GDesc Ga = { qah, qal, 128, 0,  nullptr, nullptr, 0, 0,
                 Wah, Wal, 128, 0,  b_add,   2, 0, pad, 128, 0,
                 nullptr, nullptr, 0, 0,  nullptr, nullptr };
    GDesc Gd = { qeh, qel, 128, 0,  nullptr, nullptr, 0, 0,
                 Wdh, Wdl, 128, 0,  b_df1,   2, 2, nullptr, 0, 0,
                 nullptr, nullptr, 0, 0,  W_df2, ppd };
    mma_gemm<<<dim3(MT, 3), 256, GSM>>>(128, Ge, Ga, Gd);

    scan_kernel<<<dim3(B, 2), 256>>>(init_vm);

    // summary = tanh([reads | qe] @ W_sum + b), K=256, bf16 hi/lo out
    GDesc Gs0 = { rdh, rdl, 128, 0,  qeh, qel, 128, 0,
                  Wsh, Wsl, 256, 0,    b_sum,       2, 1, nullptr, 0, 0,
                  smh, sml, 256, 0,    nullptr, nullptr };
    GDesc Gs1 = { rdh, rdl, 128, 0,  qeh, qel, 128, 0,
                  Wsh, Wsl, 256, 128,  b_sum + 128, 2, 1, nullptr, 0, 0,
                  smh, sml, 256, 128,  nullptr, nullptr };
    mma_gemm<<<dim3(MT, 2), 256, GSM>>>(256, Gs0, Gs1, Gs1);

    // ability hidden + head dot (K=256, dot-reduce per N-half)
    GDesc Gb0 = { smh, sml, 256, 0,  smh, sml, 256, 128,
                  Wbh, Wbl, 256, 0,    b_ab1,       2, 2, nullptr, 0, 0,
                  nullptr, nullptr, 0, 0,  W_ab2, ppa };
    GDesc Gb1 = { smh, sml, 256, 0,  smh, sml, 256, 128,
                  Wbh, Wbl, 256, 128,  b_ab1 + 128, 2, 2, nullptr, 0, 128,
                  nullptr, nullptr, 0, 0,  W_ab2, ppa + T };
    mma_gemm<<<dim3(MT, 2), 256, GSM>>>(256, Gb0, Gb1, Gb1);

    combine_kernel<<<T / 256, 256>>>(b_ab2, b_df2, out);
}